// round 13
// baseline (speedup 1.0000x reference)
#include <cuda_runtime.h>
#include <cuda_fp16.h>
#include <cstdint>

// Problem constants
#define NN   4096
#define FIN  512
#define FOUT 256
// C (channels) = 4

// ---------------------------------------------------------------------------
// Scratch (allocation-free rule: __device__ globals)
// ---------------------------------------------------------------------------
__device__ __half g_xh[(size_t)NN * FIN];            // 4 MB  x (fp16 hi)
__device__ __half g_wT_hi[FOUT * FIN];               // 256 KB WsumT hi
__device__ __half g_wT_lo[FOUT * FIN];               // 256 KB WsumT lo
__device__ __half g_hT[FOUT * NN];                   // 2 MB  h^T (fp16)
__device__ float  g_part[4ull * NN * FOUT];          // 16 MB split-K partials

// ---------------------------------------------------------------------------
// PTX helpers (sm_80-era only; 'a'-gated features rejected by harness ptxas)
// ---------------------------------------------------------------------------
__device__ __forceinline__ uint32_t smem_u32(const void* p) {
    uint32_t a;
    asm("{ .reg .u64 t; cvta.to.shared.u64 t, %1; cvt.u32.u64 %0, t; }"
        : "=r"(a) : "l"(p));
    return a;
}
__device__ __forceinline__ void cp16(uint32_t sdst, const void* gsrc) {
    asm volatile("cp.async.cg.shared.global [%0], [%1], 16;"
                 :: "r"(sdst), "l"(gsrc) : "memory");
}
__device__ __forceinline__ void cp_commit() {
    asm volatile("cp.async.commit_group;" ::: "memory");
}
template <int N>
__device__ __forceinline__ void cp_wait() {
    asm volatile("cp.async.wait_group %0;" :: "n"(N) : "memory");
}
__device__ __forceinline__ void ldmx4(uint32_t& r0, uint32_t& r1,
                                      uint32_t& r2, uint32_t& r3, uint32_t a) {
    asm volatile("ldmatrix.sync.aligned.m8n8.x4.shared.b16 {%0,%1,%2,%3}, [%4];"
                 : "=r"(r0), "=r"(r1), "=r"(r2), "=r"(r3) : "r"(a));
}
__device__ __forceinline__ void hmma(float* d, const uint32_t* a,
                                     const uint32_t* b) {
    asm volatile(
        "mma.sync.aligned.m16n8k16.row.col.f32.f16.f16.f32 "
        "{%0,%1,%2,%3}, {%4,%5,%6,%7}, {%8,%9}, {%0,%1,%2,%3};"
        : "+f"(d[0]), "+f"(d[1]), "+f"(d[2]), "+f"(d[3])
        : "r"(a[0]), "r"(a[1]), "r"(a[2]), "r"(a[3]), "r"(b[0]), "r"(b[1]));
}

constexpr int SROW_B = 80;   // 64B data + 16B pad (for K=32 tiles, gemm_h)

// ---------------------------------------------------------------------------
// K0a: x -> fp16 (hi only)
// ---------------------------------------------------------------------------
__global__ void x_split(const float* __restrict__ x) {
    size_t t = (size_t)blockIdx.x * blockDim.x + threadIdx.x;  // float4 idx
    float4 v = reinterpret_cast<const float4*>(x)[t];
    __half h[4] = {__float2half_rn(v.x), __float2half_rn(v.y),
                   __float2half_rn(v.z), __float2half_rn(v.w)};
    reinterpret_cast<uint2*>(g_xh)[t] = *reinterpret_cast<uint2*>(h);
}

// ---------------------------------------------------------------------------
// K0b: WsumT[j,k] = sum_c weight[k,j,c], fp16 hi/lo (transposed store)
// ---------------------------------------------------------------------------
__global__ void wsum_split(const float* __restrict__ weight) {
    int idx = blockIdx.x * blockDim.x + threadIdx.x;  // k*FOUT + j
    int k = idx >> 8, j = idx & 255;
    float4 w = reinterpret_cast<const float4*>(weight)[idx];
    float s = (w.x + w.y) + (w.z + w.w);
    __half hi = __float2half_rn(s);
    g_wT_hi[j * FIN + k] = hi;
    g_wT_lo[j * FIN + k] = __float2half_rn(s - __half2float(hi));
}

// ---------------------------------------------------------------------------
// K1: h^T[j,i] = sum_k WsumT[j,k]*x[i,k]  (2 products: Wh*xh + Wl*xh)
// CTA tile M=64(j) x N=128(i), KC=32, grid (4, 32) = 128, 3-stage cp.async.
// ---------------------------------------------------------------------------
constexpr int HF_KC    = 32;
constexpr int HF_NC    = FIN / HF_KC;                // 16
constexpr int HF_AMAT  = 64 * SROW_B;                // 5120 (per A matrix)
constexpr int HF_BMAT  = 128 * SROW_B;               // 10240
constexpr int HF_STAGE = 2 * HF_AMAT + HF_BMAT;      // 20480
constexpr int HF_SMEM  = 3 * HF_STAGE;               // 61440

__global__ __launch_bounds__(256, 1) void gemm_h_mma() {
    extern __shared__ char smem[];
    const uint32_t sb = smem_u32(smem);
    const int tid = threadIdx.x, wid = tid >> 5, lane = tid & 31;
    const int wm = wid >> 2;          // 0..1 : 32-row (j) block
    const int wn = wid & 3;           // 0..3 : 32-col (i) block
    const int m0 = blockIdx.x * 64;   // j base
    const int n0 = blockIdx.y * 128;  // i base

    float acc[2][4][4];
#pragma unroll
    for (int mi = 0; mi < 2; mi++)
#pragma unroll
        for (int ni = 0; ni < 4; ni++)
#pragma unroll
            for (int q = 0; q < 4; q++) acc[mi][ni][q] = 0.0f;

    auto load_chunk = [&](int c) {
        const uint32_t stage = sb + (uint32_t)(c % 3) * HF_STAGE;
        const int ke = c * HF_KC;
        {                                     // A: 64 rows x 64B, hi+lo
            int row = tid >> 2, c16 = tid & 3;
            uint32_t so = (uint32_t)(row * SROW_B + c16 * 16);
            size_t g = (size_t)(m0 + row) * FIN + ke + c16 * 8;
            cp16(stage + so,           g_wT_hi + g);
            cp16(stage + HF_AMAT + so, g_wT_lo + g);
        }
#pragma unroll
        for (int i = 0; i < 2; i++) {         // B: 128 rows x 64B (xh)
            int e = tid + i * 256;
            int row = e >> 2, c16 = e & 3;
            uint32_t so = (uint32_t)(row * SROW_B + c16 * 16);
            size_t g = (size_t)(n0 + row) * FIN + ke + c16 * 8;
            cp16(stage + 2 * HF_AMAT + so, g_xh + g);
        }
        cp_commit();
    };

    const uint32_t a_lane_off =
        (uint32_t)((wm * 32 + (lane & 15)) * SROW_B + ((lane >> 4) << 3) * 2);
    const uint32_t b_lane_off =
        (uint32_t)((wn * 32 + ((lane >> 4) << 3) + (lane & 7)) * SROW_B +
                   (((lane >> 3) & 1) << 3) * 2);

    load_chunk(0);
    load_chunk(1);
    load_chunk(2);

    for (int c = 0; c < HF_NC; c++) {
        {
            int rem = HF_NC - 1 - c;
            if (rem >= 2) cp_wait<2>(); else if (rem == 1) cp_wait<1>();
            else cp_wait<0>();
        }
        __syncthreads();
        const uint32_t stage = sb + (uint32_t)(c % 3) * HF_STAGE;
        const uint32_t aH = stage + a_lane_off;
        const uint32_t aL = stage + HF_AMAT + a_lane_off;
        const uint32_t bH = stage + 2 * HF_AMAT + b_lane_off;
#pragma unroll
        for (int ks = 0; ks < 2; ks++) {
            const uint32_t kb = (uint32_t)(ks * 32);
            uint32_t ah[2][4], al[2][4], bb[4][2];
#pragma unroll
            for (int mi = 0; mi < 2; mi++)
                ldmx4(ah[mi][0], ah[mi][1], ah[mi][2], ah[mi][3],
                      aH + kb + (uint32_t)(mi * 16 * SROW_B));
#pragma unroll
            for (int mi = 0; mi < 2; mi++)
                ldmx4(al[mi][0], al[mi][1], al[mi][2], al[mi][3],
                      aL + kb + (uint32_t)(mi * 16 * SROW_B));
#pragma unroll
            for (int nb = 0; nb < 2; nb++)
                ldmx4(bb[2 * nb][0], bb[2 * nb][1],
                      bb[2 * nb + 1][0], bb[2 * nb + 1][1],
                      bH + kb + (uint32_t)(nb * 16 * SROW_B));
#pragma unroll
            for (int mi = 0; mi < 2; mi++)
#pragma unroll
                for (int ni = 0; ni < 4; ni++) {
                    hmma(acc[mi][ni], ah[mi], bb[ni]);   // Wh * xh
                    hmma(acc[mi][ni], al[mi], bb[ni]);   // Wl * xh
                }
        }
        __syncthreads();
        if (c + 3 < HF_NC) load_chunk(c + 3);
    }

    // Epilogue: write h^T fp16 directly
    const int r_base = m0 + wm * 32 + (lane >> 2);       // j
    const int c_base = n0 + wn * 32 + (lane & 3) * 2;    // i
#pragma unroll
    for (int mi = 0; mi < 2; mi++)
#pragma unroll
        for (int h = 0; h < 2; h++) {
            const int j = r_base + mi * 16 + h * 8;
#pragma unroll
            for (int ni = 0; ni < 4; ni++) {
                __half2 v = __floats2half2_rn(acc[mi][ni][2 * h],
                                              acc[mi][ni][2 * h + 1]);
                *reinterpret_cast<__half2*>(
                    g_hT + (size_t)j * NN + c_base + ni * 8) = v;
            }
        }
}

// ---------------------------------------------------------------------------
// K2 (FUSED): part[sk][i,j] = sum_k (sum_c adjs[i,k,c]) * hT[j,k]
// Reads adjs RAW (268 MB HBM floor), sums 4 channels in regs, fp16, STS.
// CTA tile M=64(i) x N=256(j), 256 threads, 2 CTAs/SM, KC=16.
// Grid (NN/64=64, splitK=4) = 256 CTAs (<= 296 concurrent, one wave).
// Row stride 48B (3x16B -> conflict-free ldmatrix bank walk).
// A: reg-staged depth-1 + fp16 double buffer. B: triple-buffered cp.async.
// ---------------------------------------------------------------------------
constexpr int F_KC    = 16;
constexpr int F_NCH   = 1024 / F_KC;                 // 64 chunks
constexpr int FROW_B  = 48;                          // 32B data + 16B pad
constexpr int F_AMAT  = 64 * FROW_B;                 // 3072 (fp16 A tile)
constexpr int F_BMAT  = 256 * FROW_B;                // 12288 (fp16 B tile)
constexpr int F_SMEM  = 2 * F_AMAT + 3 * F_BMAT;     // 42 KB -> 2 CTAs/SM

__global__ __launch_bounds__(256, 2) void mma_fused_k(
    const float* __restrict__ adjs) {
    extern __shared__ char smem[];
    const uint32_t sb  = smem_u32(smem);
    const uint32_t sbB = sb + 2 * F_AMAT;
    const int tid  = threadIdx.x;
    const int wid  = tid >> 5;
    const int lane = tid & 31;
    const int wm   = wid >> 2;          // 0..1 -> 32-row (i) block
    const int wn   = wid & 3;           // 0..3 -> 64-col (j) block
    const int m0   = blockIdx.x * 64;   // i base
    const int sk   = blockIdx.y;
    const int k0   = sk * 1024;

    // A staging: thread covers cells (arow, akq..akq+3) = 64B contiguous.
    const int arow = tid >> 2;          // 0..63
    const int akq  = (tid & 3) * 4;     // 0,4,8,12

    float acc[2][8][4];
#pragma unroll
    for (int mi = 0; mi < 2; mi++)
#pragma unroll
        for (int ni = 0; ni < 8; ni++)
#pragma unroll
            for (int q = 0; q < 4; q++) acc[mi][ni][q] = 0.0f;

    float4 stg[4];

    auto ldg_stage = [&](int c) {
        const size_t base = ((size_t)(m0 + arow) * NN + k0 + c * F_KC + akq);
#pragma unroll
        for (int q = 0; q < 4; q++)
            stg[q] = reinterpret_cast<const float4*>(adjs)[base + q];
    };
    auto sts_convert = [&](int c) {
        __half h[4];
#pragma unroll
        for (int q = 0; q < 4; q++)
            h[q] = __float2half_rn((stg[q].x + stg[q].y) + (stg[q].z + stg[q].w));
        *reinterpret_cast<uint2*>(
            smem + ((c & 1) * F_AMAT + arow * FROW_B + akq * 2)) =
            *reinterpret_cast<uint2*>(h);
    };
    auto cp_b = [&](int c) {
        if (c < F_NCH) {
            const uint32_t stage = sbB + (uint32_t)(c % 3) * F_BMAT;
            const int ke = k0 + c * F_KC;
#pragma unroll
            for (int i = 0; i < 2; i++) {      // 256 rows x 2 x 16B
                int e = tid + i * 256;
                int row = e >> 1, c16 = e & 1;
                uint32_t so = (uint32_t)(row * FROW_B + c16 * 16);
                cp16(stage + so, g_hT + (size_t)row * NN + ke + c16 * 8);
            }
        }
        cp_commit();   // empty group past the end keeps counts consistent
    };

    const uint32_t a_lane_off =
        (uint32_t)((wm * 32 + (lane & 15)) * FROW_B + ((lane >> 4) << 3) * 2);
    const uint32_t b_lane_off =
        (uint32_t)((wn * 64 + ((lane >> 4) << 3) + (lane & 7)) * FROW_B +
                   (((lane >> 3) & 1) << 3) * 2);

    ldg_stage(0);
    cp_b(0);
    cp_b(1);

    for (int c = 0; c < F_NCH; c++) {
        sts_convert(c);                       // regs -> A fp16 buf (c&1)
        if (c + 1 < F_NCH) ldg_stage(c + 1);  // prefetch next A into regs
        cp_wait<2>();                         // B(c) complete
        __syncthreads();                      // STS visible, buffers safe
        cp_b(c + 2);                          // B into buf (c+2)%3 (safe now)

        const uint32_t aH = sb + (uint32_t)(c & 1) * F_AMAT + a_lane_off;
        const uint32_t bH = sbB + (uint32_t)(c % 3) * F_BMAT + b_lane_off;
        uint32_t ah[2][4], bb[8][2];
#pragma unroll
        for (int mi = 0; mi < 2; mi++)
            ldmx4(ah[mi][0], ah[mi][1], ah[mi][2], ah[mi][3],
                  aH + (uint32_t)(mi * 16 * FROW_B));
#pragma unroll
        for (int nb = 0; nb < 4; nb++)
            ldmx4(bb[2 * nb][0], bb[2 * nb][1],
                  bb[2 * nb + 1][0], bb[2 * nb + 1][1],
                  bH + (uint32_t)(nb * 16 * FROW_B));
#pragma unroll
        for (int mi = 0; mi < 2; mi++)
#pragma unroll
            for (int ni = 0; ni < 8; ni++)
                hmma(acc[mi][ni], ah[mi], bb[ni]);
    }

    // Epilogue: fp32 partials
    const int r_base = m0 + wm * 32 + (lane >> 2);       // i
    const int c_base = wn * 64 + (lane & 3) * 2;         // j
#pragma unroll
    for (int mi = 0; mi < 2; mi++)
#pragma unroll
        for (int h = 0; h < 2; h++) {
            const int row = r_base + mi * 16 + h * 8;
            float* dst = g_part + ((size_t)sk * NN + row) * FOUT + c_base;
#pragma unroll
            for (int ni = 0; ni < 8; ni++)
                *reinterpret_cast<float2*>(dst + ni * 8) =
                    make_float2(acc[mi][ni][2 * h], acc[mi][ni][2 * h + 1]);
        }
}

// ---------------------------------------------------------------------------
// Reduce: out[i,j,:] = sum_{sk<4} part[sk,i,j] + bias[i,j,:]
// ---------------------------------------------------------------------------
__global__ void reduce_kernel(const float* __restrict__ bias,
                              float* __restrict__ out) {
    const int t = blockIdx.x * blockDim.x + threadIdx.x;   // (i*256 + j)
    constexpr size_t P = (size_t)NN * FOUT;
    float s = (g_part[t] + g_part[t + P]) +
              (g_part[t + 2 * P] + g_part[t + 3 * P]);
    float4 b = reinterpret_cast<const float4*>(bias)[t];
    reinterpret_cast<float4*>(out)[t] =
        make_float4(s + b.x, s + b.y, s + b.z, s + b.w);
}

// ---------------------------------------------------------------------------
// launch
// ---------------------------------------------------------------------------
extern "C" void kernel_launch(void* const* d_in, const int* in_sizes, int n_in,
                              void* d_out, int out_size) {
    const float* x      = (const float*)d_in[0];
    const float* adjs   = (const float*)d_in[1];
    const float* weight = (const float*)d_in[2];
    const float* bias   = (const float*)d_in[3];
    float* out          = (float*)d_out;

    cudaFuncSetAttribute(gemm_h_mma,
                         cudaFuncAttributeMaxDynamicSharedMemorySize, HF_SMEM);
    cudaFuncSetAttribute(mma_fused_k,
                         cudaFuncAttributeMaxDynamicSharedMemorySize, F_SMEM);

    // Prep: x -> fp16, WsumT hi/lo
    x_split<<<(NN * FIN / 4) / 256, 256>>>(x);
    wsum_split<<<(FIN * FOUT) / 256, 256>>>(weight);
    // h^T = WsumT @ x^T  (HMMA, 2 products)
    gemm_h_mma<<<dim3(FOUT / 64, NN / 128), 256, HF_SMEM>>>();
    // Main fused GEMM: channel-sum + fp16 convert + HMMA, split-K=4,
    // 2 CTAs/SM for sync/stream overlap
    mma_fused_k<<<dim3(NN / 64, 4), 256, F_SMEM>>>(adjs);
    // Combine partials + bias
    reduce_kernel<<<(NN * FOUT) / 256, 256>>>(bias, out);
}

// round 14
// speedup vs baseline: 1.0429x; 1.0429x over previous
#include <cuda_runtime.h>
#include <cuda_fp16.h>
#include <cstdint>

// Problem constants
#define NN   4096
#define FIN  512
#define FOUT 256
// C (channels) = 4

// ---------------------------------------------------------------------------
// Scratch (allocation-free rule: __device__ globals)
// ---------------------------------------------------------------------------
__device__ __half g_xh[(size_t)NN * FIN];            // 4 MB  x (fp16 hi)
__device__ __half g_wT_hi[FOUT * FIN];               // 256 KB WsumT hi
__device__ __half g_wT_lo[FOUT * FIN];               // 256 KB WsumT lo
__device__ __half g_hT[FOUT * NN];                   // 2 MB  h^T (fp16)
__device__ float  g_part[4ull * NN * FOUT];          // 16 MB split-K partials

// ---------------------------------------------------------------------------
// PTX helpers (sm_80-era only; 'a'-gated features rejected by harness ptxas)
// ---------------------------------------------------------------------------
__device__ __forceinline__ uint32_t smem_u32(const void* p) {
    uint32_t a;
    asm("{ .reg .u64 t; cvta.to.shared.u64 t, %1; cvt.u32.u64 %0, t; }"
        : "=r"(a) : "l"(p));
    return a;
}
__device__ __forceinline__ void cp16(uint32_t sdst, const void* gsrc) {
    asm volatile("cp.async.cg.shared.global [%0], [%1], 16;"
                 :: "r"(sdst), "l"(gsrc) : "memory");
}
__device__ __forceinline__ void cp_commit() {
    asm volatile("cp.async.commit_group;" ::: "memory");
}
template <int N>
__device__ __forceinline__ void cp_wait() {
    asm volatile("cp.async.wait_group %0;" :: "n"(N) : "memory");
}
__device__ __forceinline__ void ldmx4(uint32_t& r0, uint32_t& r1,
                                      uint32_t& r2, uint32_t& r3, uint32_t a) {
    asm volatile("ldmatrix.sync.aligned.m8n8.x4.shared.b16 {%0,%1,%2,%3}, [%4];"
                 : "=r"(r0), "=r"(r1), "=r"(r2), "=r"(r3) : "r"(a));
}
__device__ __forceinline__ void hmma(float* d, const uint32_t* a,
                                     const uint32_t* b) {
    asm volatile(
        "mma.sync.aligned.m16n8k16.row.col.f32.f16.f16.f32 "
        "{%0,%1,%2,%3}, {%4,%5,%6,%7}, {%8,%9}, {%0,%1,%2,%3};"
        : "+f"(d[0]), "+f"(d[1]), "+f"(d[2]), "+f"(d[3])
        : "r"(a[0]), "r"(a[1]), "r"(a[2]), "r"(a[3]), "r"(b[0]), "r"(b[1]));
}

constexpr int SROW_B = 80;   // 64B data + 16B pad (K=32 tiles, gemm_h)

// ---------------------------------------------------------------------------
// K0a: x -> fp16 (hi only)
// ---------------------------------------------------------------------------
__global__ void x_split(const float* __restrict__ x) {
    size_t t = (size_t)blockIdx.x * blockDim.x + threadIdx.x;  // float4 idx
    float4 v = reinterpret_cast<const float4*>(x)[t];
    __half h[4] = {__float2half_rn(v.x), __float2half_rn(v.y),
                   __float2half_rn(v.z), __float2half_rn(v.w)};
    reinterpret_cast<uint2*>(g_xh)[t] = *reinterpret_cast<uint2*>(h);
}

// ---------------------------------------------------------------------------
// K0b: WsumT[j,k] = sum_c weight[k,j,c], fp16 hi/lo (transposed store)
// ---------------------------------------------------------------------------
__global__ void wsum_split(const float* __restrict__ weight) {
    int idx = blockIdx.x * blockDim.x + threadIdx.x;  // k*FOUT + j
    int k = idx >> 8, j = idx & 255;
    float4 w = reinterpret_cast<const float4*>(weight)[idx];
    float s = (w.x + w.y) + (w.z + w.w);
    __half hi = __float2half_rn(s);
    g_wT_hi[j * FIN + k] = hi;
    g_wT_lo[j * FIN + k] = __float2half_rn(s - __half2float(hi));
}

// ---------------------------------------------------------------------------
// K1: h^T[j,i] = sum_k WsumT[j,k]*x[i,k]  (2 products: Wh*xh + Wl*xh)
// CTA tile M=64(j) x N=128(i), KC=32, grid (4, 32) = 128, 3-stage cp.async.
// ---------------------------------------------------------------------------
constexpr int HF_KC    = 32;
constexpr int HF_NC    = FIN / HF_KC;                // 16
constexpr int HF_AMAT  = 64 * SROW_B;                // 5120 (per A matrix)
constexpr int HF_BMAT  = 128 * SROW_B;               // 10240
constexpr int HF_STAGE = 2 * HF_AMAT + HF_BMAT;      // 20480
constexpr int HF_SMEM  = 3 * HF_STAGE;               // 61440

__global__ __launch_bounds__(256, 1) void gemm_h_mma() {
    extern __shared__ char smem[];
    const uint32_t sb = smem_u32(smem);
    const int tid = threadIdx.x, wid = tid >> 5, lane = tid & 31;
    const int wm = wid >> 2;          // 0..1 : 32-row (j) block
    const int wn = wid & 3;           // 0..3 : 32-col (i) block
    const int m0 = blockIdx.x * 64;   // j base
    const int n0 = blockIdx.y * 128;  // i base

    float acc[2][4][4];
#pragma unroll
    for (int mi = 0; mi < 2; mi++)
#pragma unroll
        for (int ni = 0; ni < 4; ni++)
#pragma unroll
            for (int q = 0; q < 4; q++) acc[mi][ni][q] = 0.0f;

    auto load_chunk = [&](int c) {
        const uint32_t stage = sb + (uint32_t)(c % 3) * HF_STAGE;
        const int ke = c * HF_KC;
        {                                     // A: 64 rows x 64B, hi+lo
            int row = tid >> 2, c16 = tid & 3;
            uint32_t so = (uint32_t)(row * SROW_B + c16 * 16);
            size_t g = (size_t)(m0 + row) * FIN + ke + c16 * 8;
            cp16(stage + so,           g_wT_hi + g);
            cp16(stage + HF_AMAT + so, g_wT_lo + g);
        }
#pragma unroll
        for (int i = 0; i < 2; i++) {         // B: 128 rows x 64B (xh)
            int e = tid + i * 256;
            int row = e >> 2, c16 = e & 3;
            uint32_t so = (uint32_t)(row * SROW_B + c16 * 16);
            size_t g = (size_t)(n0 + row) * FIN + ke + c16 * 8;
            cp16(stage + 2 * HF_AMAT + so, g_xh + g);
        }
        cp_commit();
    };

    const uint32_t a_lane_off =
        (uint32_t)((wm * 32 + (lane & 15)) * SROW_B + ((lane >> 4) << 3) * 2);
    const uint32_t b_lane_off =
        (uint32_t)((wn * 32 + ((lane >> 4) << 3) + (lane & 7)) * SROW_B +
                   (((lane >> 3) & 1) << 3) * 2);

    load_chunk(0);
    load_chunk(1);
    load_chunk(2);

    for (int c = 0; c < HF_NC; c++) {
        {
            int rem = HF_NC - 1 - c;
            if (rem >= 2) cp_wait<2>(); else if (rem == 1) cp_wait<1>();
            else cp_wait<0>();
        }
        __syncthreads();
        const uint32_t stage = sb + (uint32_t)(c % 3) * HF_STAGE;
        const uint32_t aH = stage + a_lane_off;
        const uint32_t aL = stage + HF_AMAT + a_lane_off;
        const uint32_t bH = stage + 2 * HF_AMAT + b_lane_off;
#pragma unroll
        for (int ks = 0; ks < 2; ks++) {
            const uint32_t kb = (uint32_t)(ks * 32);
            uint32_t ah[2][4], al[2][4], bb[4][2];
#pragma unroll
            for (int mi = 0; mi < 2; mi++)
                ldmx4(ah[mi][0], ah[mi][1], ah[mi][2], ah[mi][3],
                      aH + kb + (uint32_t)(mi * 16 * SROW_B));
#pragma unroll
            for (int mi = 0; mi < 2; mi++)
                ldmx4(al[mi][0], al[mi][1], al[mi][2], al[mi][3],
                      aL + kb + (uint32_t)(mi * 16 * SROW_B));
#pragma unroll
            for (int nb = 0; nb < 2; nb++)
                ldmx4(bb[2 * nb][0], bb[2 * nb][1],
                      bb[2 * nb + 1][0], bb[2 * nb + 1][1],
                      bH + kb + (uint32_t)(nb * 16 * SROW_B));
#pragma unroll
            for (int mi = 0; mi < 2; mi++)
#pragma unroll
                for (int ni = 0; ni < 4; ni++) {
                    hmma(acc[mi][ni], ah[mi], bb[ni]);   // Wh * xh
                    hmma(acc[mi][ni], al[mi], bb[ni]);   // Wl * xh
                }
        }
        __syncthreads();
        if (c + 3 < HF_NC) load_chunk(c + 3);
    }

    // Epilogue: write h^T fp16 directly
    const int r_base = m0 + wm * 32 + (lane >> 2);       // j
    const int c_base = n0 + wn * 32 + (lane & 3) * 2;    // i
#pragma unroll
    for (int mi = 0; mi < 2; mi++)
#pragma unroll
        for (int h = 0; h < 2; h++) {
            const int j = r_base + mi * 16 + h * 8;
#pragma unroll
            for (int ni = 0; ni < 4; ni++) {
                __half2 v = __floats2half2_rn(acc[mi][ni][2 * h],
                                              acc[mi][ni][2 * h + 1]);
                *reinterpret_cast<__half2*>(
                    g_hT + (size_t)j * NN + c_base + ni * 8) = v;
            }
        }
}

// ---------------------------------------------------------------------------
// K2 (FUSED v3): part[sk][i,j] = sum_k (sum_c adjs[i,k,c]) * hT[j,k]
// A path is BARRIER-FREE: each lane LDGs the 8 float4s whose channel-sums
// form its m16k16 HMMA A-fragment, sums + converts in registers (no A smem).
// B: KC=64 stages (256 x 128B, 144B stride), 4-deep cp.async ring,
// one __syncthreads per stage (per 4 chunks).
// CTA: M=128(i) x N=256(j), 512 thr, 16 warps (warp tile 16x128), splitK=4.
// ---------------------------------------------------------------------------
constexpr int F_KC    = 16;                          // A chunk (one k16 MMA)
constexpr int F_NCH   = 1024 / F_KC;                 // 64 chunks
constexpr int FB_KC   = 64;                          // B stage K width
constexpr int FB_NST  = 1024 / FB_KC;                // 16 B stages
constexpr int FB_ROW  = 144;                         // 128B data + 16B pad
constexpr int FB_MAT  = 256 * FB_ROW;                // 36864 per stage
constexpr int F_SMEM  = 4 * FB_MAT;                  // 147456

__global__ __launch_bounds__(512, 1) void mma_fused_k(
    const float* __restrict__ adjs) {
    extern __shared__ char smem[];
    const uint32_t sb = smem_u32(smem);
    const int tid  = threadIdx.x;
    const int wid  = tid >> 5;
    const int lane = tid & 31;
    const int wm   = wid >> 1;          // 0..7 -> 16-row (i) block
    const int wn   = wid & 1;           // 0..1 -> 128-col (j) block
    const int m0   = blockIdx.x * 128;  // i base
    const int sk   = blockIdx.y;
    const int k0   = sk * 1024;

    float acc[16][4];
#pragma unroll
    for (int ni = 0; ni < 16; ni++)
#pragma unroll
        for (int q = 0; q < 4; q++) acc[ni][q] = 0.0f;

    // A fragment LDG map (float4 units; adjs cell (i,k) = float4 [i*NN + k])
    const float4* __restrict__ A4 = reinterpret_cast<const float4*>(adjs);
    const size_t ar0 = (size_t)(m0 + wm * 16 + (lane >> 2)) * NN;  // row i
    const size_t ar8 = ar0 + (size_t)8 * NN;                        // row i+8
    const int    kcb = k0 + 2 * (lane & 3);                         // col base

    float4 stg[8];
    auto ldg_a = [&](int c) {
        const size_t k = (size_t)(kcb + c * F_KC);
        stg[0] = A4[ar0 + k];     stg[1] = A4[ar0 + k + 1];
        stg[2] = A4[ar8 + k];     stg[3] = A4[ar8 + k + 1];
        stg[4] = A4[ar0 + k + 8]; stg[5] = A4[ar0 + k + 9];
        stg[6] = A4[ar8 + k + 8]; stg[7] = A4[ar8 + k + 9];
    };
    auto cvt_a = [&](uint32_t* af) {
        float s[8];
#pragma unroll
        for (int q = 0; q < 8; q++)
            s[q] = (stg[q].x + stg[q].y) + (stg[q].z + stg[q].w);
        __half2 p0 = __floats2half2_rn(s[0], s[1]);
        __half2 p1 = __floats2half2_rn(s[2], s[3]);
        __half2 p2 = __floats2half2_rn(s[4], s[5]);
        __half2 p3 = __floats2half2_rn(s[6], s[7]);
        af[0] = *reinterpret_cast<uint32_t*>(&p0);
        af[1] = *reinterpret_cast<uint32_t*>(&p1);
        af[2] = *reinterpret_cast<uint32_t*>(&p2);
        af[3] = *reinterpret_cast<uint32_t*>(&p3);
    };

    // B stage loader: 256 rows x 128B, 4 x cp16 per thread
    auto cp_b = [&](int bs) {
        if (bs < FB_NST) {
            const uint32_t stage = sb + (uint32_t)(bs & 3) * FB_MAT;
            const int ke = k0 + bs * FB_KC;
#pragma unroll
            for (int i = 0; i < 4; i++) {
                int e = tid + i * 512;
                int row = e >> 3, c16 = e & 7;
                uint32_t so = (uint32_t)(row * FB_ROW + c16 * 16);
                cp16(stage + so, g_hT + (size_t)row * NN + ke + c16 * 8);
            }
        }
        cp_commit();   // empty groups past the end keep wait counts aligned
    };

    // B ldmatrix lane offset (row part; k byte offset added per chunk)
    const uint32_t b_lane_row =
        (uint32_t)((wn * 128 + ((lane >> 4) << 3) + (lane & 7)) * FB_ROW);
    const uint32_t b_lane_k8 = (uint32_t)((((lane >> 3) & 1) << 3) * 2);

    ldg_a(0);
    cp_b(0); cp_b(1); cp_b(2);

    for (int bs = 0; bs < FB_NST; bs++) {
        cp_wait<2>();          // stage bs complete (bs+1, bs+2 in flight)
        __syncthreads();       // all warps done with stage (bs+3)&3's buffer
        cp_b(bs + 3);

        const uint32_t stage = sb + (uint32_t)(bs & 3) * FB_MAT;
#pragma unroll
        for (int cc = 0; cc < 4; cc++) {
            const int c = bs * 4 + cc;
            uint32_t af[4];
            cvt_a(af);                         // stg -> A fragment
            if (c + 1 < F_NCH) ldg_a(c + 1);   // prefetch next A chunk
            const uint32_t bbase =
                stage + b_lane_row + (uint32_t)(cc * 32) + b_lane_k8;
#pragma unroll
            for (int nb = 0; nb < 8; nb++) {
                uint32_t bb[2][2];
                ldmx4(bb[0][0], bb[0][1], bb[1][0], bb[1][1],
                      bbase + (uint32_t)(nb * 16 * FB_ROW));
                hmma(acc[2 * nb],     af, bb[0]);
                hmma(acc[2 * nb + 1], af, bb[1]);
            }
        }
    }

    // Epilogue: fp32 partials
    const int r_base = m0 + wm * 16 + (lane >> 2);       // i
    const int c_base = wn * 128 + (lane & 3) * 2;        // j
#pragma unroll
    for (int h = 0; h < 2; h++) {
        const int row = r_base + h * 8;
        float* dst = g_part + ((size_t)sk * NN + row) * FOUT + c_base;
#pragma unroll
        for (int ni = 0; ni < 16; ni++)
            *reinterpret_cast<float2*>(dst + ni * 8) =
                make_float2(acc[ni][2 * h], acc[ni][2 * h + 1]);
    }
}

// ---------------------------------------------------------------------------
// Reduce: out[i,j,:] = sum_{sk<4} part[sk,i,j] + bias[i,j,:]
// ---------------------------------------------------------------------------
__global__ void reduce_kernel(const float* __restrict__ bias,
                              float* __restrict__ out) {
    const int t = blockIdx.x * blockDim.x + threadIdx.x;   // (i*256 + j)
    constexpr size_t P = (size_t)NN * FOUT;
    float s = (g_part[t] + g_part[t + P]) +
              (g_part[t + 2 * P] + g_part[t + 3 * P]);
    float4 b = reinterpret_cast<const float4*>(bias)[t];
    reinterpret_cast<float4*>(out)[t] =
        make_float4(s + b.x, s + b.y, s + b.z, s + b.w);
}

// ---------------------------------------------------------------------------
// launch
// ---------------------------------------------------------------------------
extern "C" void kernel_launch(void* const* d_in, const int* in_sizes, int n_in,
                              void* d_out, int out_size) {
    const float* x      = (const float*)d_in[0];
    const float* adjs   = (const float*)d_in[1];
    const float* weight = (const float*)d_in[2];
    const float* bias   = (const float*)d_in[3];
    float* out          = (float*)d_out;

    cudaFuncSetAttribute(gemm_h_mma,
                         cudaFuncAttributeMaxDynamicSharedMemorySize, HF_SMEM);
    cudaFuncSetAttribute(mma_fused_k,
                         cudaFuncAttributeMaxDynamicSharedMemorySize, F_SMEM);

    // Prep: x -> fp16, WsumT hi/lo
    x_split<<<(NN * FIN / 4) / 256, 256>>>(x);
    wsum_split<<<(FIN * FOUT) / 256, 256>>>(weight);
    // h^T = WsumT @ x^T  (HMMA, 2 products)
    gemm_h_mma<<<dim3(FOUT / 64, NN / 128), 256, HF_SMEM>>>();
    // Main fused GEMM: barrier-free A (LDG->fragment), splitK=4, grid 128
    mma_fused_k<<<dim3(NN / 128, 4), 512, F_SMEM>>>(adjs);
    // Combine partials + bias
    reduce_kernel<<<(NN * FOUT) / 256, 256>>>(bias, out);
}